// round 14
// baseline (speedup 1.0000x reference)
#include <cuda_runtime.h>
#include <cuda_bf16.h>

#define BT 64
#define CH 256
#define HH 64
#define WW 64
#define JJ 17
#define NP 4
#define NPTS (BT * JJ)
#define PPB 2                    // points per block
#define NBLK (NPTS / PPB)        // 544 blocks

struct Geom {
    int x0, y0;
    int yc0, yc1, bc, o0, o1;
    bool have_e;
    float w00, w01, w10, w11;
};

__device__ __forceinline__ Geom make_geom(float gx, float gy) {
    Geom g;
    float x = (gx + 1.0f) * 0.5f * (float)(WW - 1);
    float y = (gy + 1.0f) * 0.5f * (float)(HH - 1);
    float x0f = floorf(x), y0f = floorf(y);
    float wx1 = x - x0f, wx0 = 1.0f - wx1;
    float wy1 = y - y0f, wy0 = 1.0f - wy1;
    g.x0 = (int)x0f; g.y0 = (int)y0f;
    int x0 = g.x0, y0 = g.y0;
    int x1 = x0 + 1, y1 = y0 + 1;
    float vx0 = (x0 >= 0 && x0 <= WW - 1) ? 1.0f : 0.0f;
    float vx1 = (x1 >= 0 && x1 <= WW - 1) ? 1.0f : 0.0f;
    float vy0 = (y0 >= 0 && y0 <= HH - 1) ? 1.0f : 0.0f;
    float vy1 = (y1 >= 0 && y1 <= HH - 1) ? 1.0f : 0.0f;
    int xc0 = min(max(x0, 0), WW - 1);
    int xc1 = min(max(x1, 0), WW - 1);
    g.yc0 = min(max(y0, 0), HH - 1);
    g.yc1 = min(max(y1, 0), HH - 1);
    g.bc  = xc0 & ~3;
    g.o0  = xc0 - g.bc;
    g.o1  = xc1 - g.bc;
    g.have_e = (g.o1 == 4);
    g.w00 = wx0 * wy0 * vx0 * vy0;
    g.w01 = wx1 * wy0 * vx1 * vy0;
    g.w10 = wx0 * wy1 * vx0 * vy1;
    g.w11 = wx1 * wy1 * vx1 * vy1;
    return g;
}

__device__ __forceinline__ float sel4(float4 q, int i) {
    float r = q.x;
    if (i == 1) r = q.y;
    else if (i == 2) r = q.z;
    else if (i == 3) r = q.w;
    return r;
}
__device__ __forceinline__ float pick5(float4 q, float e, int i) {
    return (i == 4) ? e : sel4(q, i);
}

// ───────────── Fully fused kernel: 544 blocks x 256 threads, 2 points each ─────────────
#define KT 64
__global__ __launch_bounds__(256)
void fused(const float* __restrict__ feat, const float* __restrict__ kp,
           const float* __restrict__ w1, const float* __restrict__ b1,
           const float* __restrict__ w2, const float* __restrict__ b2,
           float* __restrict__ out)
{
    __shared__ float s_w1t[KT][129];                  // 33 KB transposed w1 tile
    __shared__ __align__(16) float s_seed[PPB][CH];   // 2 KB
    __shared__ float s_part[2][128][PPB + 1];         // 3 KB
    __shared__ __align__(16) float s_h[PPB][128];     // 1 KB
    __shared__ float  s_grid[PPB][2 * NP];
    __shared__ int2   s_cell[PPB];                    // seed cell (x0, y0)
    __shared__ float4 s_w[PPB][NP];                   // plan: combined weights
    __shared__ int4   s_cd[PPB][NP];                  // plan: fallback coords
    __shared__ int    s_fast[PPB][NP];

    const int tid = threadIdx.x;
    const int c   = tid;
    const int p0  = blockIdx.x * PPB;

    // ---- Stage 1: gather windows, compute seeds + register corner quads ----
    float4 cv[PPB];
    unsigned planeoff[PPB];
    #pragma unroll
    for (int p = 0; p < PPB; p++) {
        const int pt = p0 + p;
        const float gx = __ldg(kp + pt * 2 + 0);
        const float gy = __ldg(kp + pt * 2 + 1);
        Geom g = make_geom(gx, gy);
        planeoff[p] = ((unsigned)(pt / JJ) * CH + c) * (HH * WW);
        const float* plane = feat + planeoff[p];
        const float* r0 = plane + g.yc0 * WW;
        const float* r1 = plane + g.yc1 * WW;
        float4 q0 = __ldg((const float4*)(r0 + g.bc));
        float4 q1 = __ldg((const float4*)(r1 + g.bc));
        float e0 = 0.0f, e1 = 0.0f;
        if (g.have_e) {                    // block-uniform
            e0 = __ldg(r0 + g.bc + 4);
            e1 = __ldg(r1 + g.bc + 4);
        }
        cv[p] = make_float4(sel4(q0, g.o0), pick5(q0, e0, g.o1),
                            sel4(q1, g.o0), pick5(q1, e1, g.o1));
        s_seed[p][c] = cv[p].x * g.w00 + cv[p].y * g.w01
                     + cv[p].z * g.w10 + cv[p].w * g.w11;
        if (c == 0) s_cell[p] = make_int2(g.x0, g.y0);
    }

    // ---- Stage 2: layer 1 GEMM (256->128, relu) over 2 points ----
    const int o = tid & 127;
    const int h = tid >> 7;
    float acc[PPB] = {0, 0};

    for (int t = 0; t < CH / KT; t++) {
        __syncthreads();
        #pragma unroll
        for (int j = 0; j < 8; j++) {
            int L  = tid + j * 256;
            int oo = L >> 4;
            int k4 = L & 15;
            float4 v = __ldg((const float4*)(w1 + oo * CH + t * KT) + k4);
            s_w1t[k4 * 4 + 0][oo] = v.x;
            s_w1t[k4 * 4 + 1][oo] = v.y;
            s_w1t[k4 * 4 + 2][oo] = v.z;
            s_w1t[k4 * 4 + 3][oo] = v.w;
        }
        __syncthreads();

        #pragma unroll
        for (int kb = 0; kb < 4; kb++) {
            float wv[8];
            #pragma unroll
            for (int u = 0; u < 8; u++)
                wv[u] = s_w1t[h * 32 + kb * 8 + u][o];
            const int ch = t * KT + h * 32 + kb * 8;
            #pragma unroll
            for (int p = 0; p < PPB; p++) {
                float4 s0 = *(const float4*)&s_seed[p][ch];
                float4 s1 = *(const float4*)&s_seed[p][ch + 4];
                acc[p] += wv[0] * s0.x + wv[1] * s0.y + wv[2] * s0.z + wv[3] * s0.w
                        + wv[4] * s1.x + wv[5] * s1.y + wv[6] * s1.z + wv[7] * s1.w;
            }
        }
    }
    #pragma unroll
    for (int p = 0; p < PPB; p++) s_part[h][o][p] = acc[p];
    __syncthreads();

    if (tid < 128) {
        float bias = __ldg(b1 + tid);
        #pragma unroll
        for (int p = 0; p < PPB; p++)
            s_h[p][tid] = fmaxf(s_part[0][tid][p] + s_part[1][tid][p] + bias, 0.0f);
    }
    __syncthreads();

    // ---- Stage 3: layer 2 (128->8) -> s_grid (2 pts x 8 outputs x 8 slices) ----
    if (tid < PPB * 64) {
        const int p  = tid >> 6;          // point
        const int r  = tid & 63;
        const int oo = r >> 3;            // output (= n*2 + d)
        const int j  = r & 7;             // k-slice
        const float4* w2r = (const float4*)w2 + oo * 32 + j * 4;
        const float4* hr  = (const float4*)s_h[p] + j * 4;
        float a = 0.0f;
        #pragma unroll
        for (int i = 0; i < 4; i++) {
            float4 w = __ldg(w2r + i);
            float4 hh = hr[i];
            a += w.x * hh.x + w.y * hh.y + w.z * hh.z + w.w * hh.w;
        }
        a += __shfl_down_sync(0xffffffffu, a, 4, 8);
        a += __shfl_down_sync(0xffffffffu, a, 2, 8);
        a += __shfl_down_sync(0xffffffffu, a, 1, 8);
        if (j == 0) {
            const int pt = p0 + p;
            a += __ldg(b2 + oo);
            int d = oo & 1;
            float scale = (d == 0) ? (2.0f / (WW - 1)) : (2.0f / (HH - 1));
            float base  = __ldg(kp + pt * 2 + d);
            s_grid[p][oo] = base + a * scale;
        }
    }
    __syncthreads();

    // ---- Stage 4: sampling plan (threads 0..7: 2 pts x 4 deformed points) ----
    if (tid < PPB * NP) {
        const int p = tid >> 2;
        const int n = tid & 3;
        float dgx = s_grid[p][n * 2 + 0];
        float dgy = s_grid[p][n * 2 + 1];
        float xx = (dgx + 1.0f) * 0.5f * (float)(WW - 1);
        float yy = (dgy + 1.0f) * 0.5f * (float)(HH - 1);
        float xf = floorf(xx), yf = floorf(yy);
        float ax1 = xx - xf, ax0 = 1.0f - ax1;
        float ay1 = yy - yf, ay0 = 1.0f - ay1;
        int dx0 = (int)xf, dy0 = (int)yf;
        int dx1 = dx0 + 1, dy1 = dy0 + 1;

        float ux0 = (dx0 >= 0 && dx0 <= WW - 1) ? 1.0f : 0.0f;
        float ux1 = (dx1 >= 0 && dx1 <= WW - 1) ? 1.0f : 0.0f;
        float uy0 = (dy0 >= 0 && dy0 <= HH - 1) ? 1.0f : 0.0f;
        float uy1 = (dy1 >= 0 && dy1 <= HH - 1) ? 1.0f : 0.0f;

        s_w[p][n] = make_float4(ax0 * ay0 * ux0 * uy0,
                                ax1 * ay0 * ux1 * uy0,
                                ax0 * ay1 * ux0 * uy1,
                                ax1 * ay1 * ux1 * uy1);
        s_fast[p][n] = (dx0 == s_cell[p].x) && (dy0 == s_cell[p].y);

        int xc0 = min(max(dx0, 0), WW - 1);
        int xc1 = min(max(dx1, 0), WW - 1);
        int yc0 = min(max(dy0, 0), HH - 1);
        int yc1 = min(max(dy1, 0), HH - 1);
        s_cd[p][n] = make_int4(yc0 * WW, yc1 * WW, xc0, xc1);
    }
    __syncthreads();

    // ---- Stage 5: resample + coalesced channel-last writes ----
    #pragma unroll
    for (int p = 0; p < PPB; p++) {
        const int pt = p0 + p;
        const float* plane = feat + planeoff[p];
        float* obase = out + (size_t)pt * (NP * CH) + c;
        #pragma unroll
        for (int n = 0; n < NP; n++) {
            float4 w = s_w[p][n];
            float r;
            if (s_fast[p][n]) {           // block-uniform branch
                r = cv[p].x * w.x + cv[p].y * w.y + cv[p].z * w.z + cv[p].w * w.w;
            } else {
                int4 cd = s_cd[p][n];
                float v00 = __ldg(plane + cd.x + cd.z);
                float v01 = __ldg(plane + cd.x + cd.w);
                float v10 = __ldg(plane + cd.y + cd.z);
                float v11 = __ldg(plane + cd.y + cd.w);
                r = v00 * w.x + v01 * w.y + v10 * w.z + v11 * w.w;
            }
            obase[n * CH] = r;
        }
    }
}

extern "C" void kernel_launch(void* const* d_in, const int* in_sizes, int n_in,
                              void* d_out, int out_size)
{
    const float* feat = (const float*)d_in[0];   // [64,256,64,64]
    const float* kp   = (const float*)d_in[1];   // [64,17,2]
    const float* w1   = (const float*)d_in[2];   // [128,256]
    const float* b1   = (const float*)d_in[3];   // [128]
    const float* w2   = (const float*)d_in[4];   // [8,128]
    const float* b2   = (const float*)d_in[5];   // [8]
    float* out = (float*)d_out;                  // [64,17,1024]

    fused<<<NBLK, 256>>>(feat, kp, w1, b1, w2, b2, out);
}

// round 15
// speedup vs baseline: 1.2775x; 1.2775x over previous
#include <cuda_runtime.h>
#include <cuda_bf16.h>

#define BT 64
#define CH 256
#define HH 64
#define WW 64
#define JJ 17
#define NP 4
#define NPTS (BT * JJ)
#define PPB 4                    // points per block
#define NBLK (NPTS / PPB)        // 272 blocks
#define KT 64                    // channels per w1 tile
#define TSTRIDE 68               // row stride (68 mod 32 == 4 -> conflict-free float4 LDS)
#define TILE_FLOATS (128 * TSTRIDE)
#define DSMEM_BYTES (2 * TILE_FLOATS * 4)   // 69,632 B

struct Geom {
    int x0, y0;
    int yc0, yc1, bc, o0, o1;
    bool have_e;
    float w00, w01, w10, w11;
};

__device__ __forceinline__ Geom make_geom(float gx, float gy) {
    Geom g;
    float x = (gx + 1.0f) * 0.5f * (float)(WW - 1);
    float y = (gy + 1.0f) * 0.5f * (float)(HH - 1);
    float x0f = floorf(x), y0f = floorf(y);
    float wx1 = x - x0f, wx0 = 1.0f - wx1;
    float wy1 = y - y0f, wy0 = 1.0f - wy1;
    g.x0 = (int)x0f; g.y0 = (int)y0f;
    int x0 = g.x0, y0 = g.y0;
    int x1 = x0 + 1, y1 = y0 + 1;
    float vx0 = (x0 >= 0 && x0 <= WW - 1) ? 1.0f : 0.0f;
    float vx1 = (x1 >= 0 && x1 <= WW - 1) ? 1.0f : 0.0f;
    float vy0 = (y0 >= 0 && y0 <= HH - 1) ? 1.0f : 0.0f;
    float vy1 = (y1 >= 0 && y1 <= HH - 1) ? 1.0f : 0.0f;
    int xc0 = min(max(x0, 0), WW - 1);
    int xc1 = min(max(x1, 0), WW - 1);
    g.yc0 = min(max(y0, 0), HH - 1);
    g.yc1 = min(max(y1, 0), HH - 1);
    g.bc  = xc0 & ~3;
    g.o0  = xc0 - g.bc;
    g.o1  = xc1 - g.bc;
    g.have_e = (g.o1 == 4);
    g.w00 = wx0 * wy0 * vx0 * vy0;
    g.w01 = wx1 * wy0 * vx1 * vy0;
    g.w10 = wx0 * wy1 * vx0 * vy1;
    g.w11 = wx1 * wy1 * vx1 * vy1;
    return g;
}

__device__ __forceinline__ float sel4(float4 q, int i) {
    float r = q.x;
    if (i == 1) r = q.y;
    else if (i == 2) r = q.z;
    else if (i == 3) r = q.w;
    return r;
}
__device__ __forceinline__ float pick5(float4 q, float e, int i) {
    return (i == 4) ? e : sel4(q, i);
}

// async-copy one KT-channel w1 tile into smem (row-major [128][TSTRIDE])
__device__ __forceinline__ void fill_tile_async(
    const float* __restrict__ w1, int t, float* tile, int tid)
{
    unsigned dst_base = (unsigned)__cvta_generic_to_shared(tile);
    #pragma unroll
    for (int j = 0; j < 8; j++) {
        int L  = tid + j * 256;          // 0..2047 float4 chunks
        int oo = L >> 4;                 // output row
        int k4 = L & 15;                 // float4 within row
        const float* src = w1 + oo * CH + t * KT + k4 * 4;
        unsigned dst = dst_base + (oo * TSTRIDE + k4 * 4) * 4;
        asm volatile("cp.async.ca.shared.global [%0], [%1], 16;"
                     :: "r"(dst), "l"(src) : "memory");
    }
    asm volatile("cp.async.commit_group;" ::: "memory");
}

// ───────────── Fully fused kernel: 272 blocks x 256 threads, 4 points each ─────────────
__global__ __launch_bounds__(256)
void fused(const float* __restrict__ feat, const float* __restrict__ kp,
           const float* __restrict__ w1, const float* __restrict__ b1,
           const float* __restrict__ w2, const float* __restrict__ b2,
           float* __restrict__ out)
{
    extern __shared__ float s_w1d[];                  // 2 x [128][TSTRIDE]
    __shared__ __align__(16) float s_seed[PPB][CH];   // 4 KB
    __shared__ float s_part[2][128][PPB + 1];         // 5 KB
    __shared__ __align__(16) float s_h[PPB][128];     // 2 KB
    __shared__ float  s_grid[PPB][2 * NP];
    __shared__ int2   s_cell[PPB];
    __shared__ float4 s_w[PPB][NP];
    __shared__ int4   s_cd[PPB][NP];
    __shared__ int    s_fast[PPB][NP];

    const int tid = threadIdx.x;
    const int c   = tid;
    const int p0  = blockIdx.x * PPB;

    // ---- Stage 1: gather windows, compute seeds + register corner quads ----
    float4 cv[PPB];
    unsigned planeoff[PPB];
    #pragma unroll
    for (int p = 0; p < PPB; p++) {
        const int pt = p0 + p;
        const float gx = __ldg(kp + pt * 2 + 0);
        const float gy = __ldg(kp + pt * 2 + 1);
        Geom g = make_geom(gx, gy);
        planeoff[p] = ((unsigned)(pt / JJ) * CH + c) * (HH * WW);
        const float* plane = feat + planeoff[p];
        const float* r0 = plane + g.yc0 * WW;
        const float* r1 = plane + g.yc1 * WW;
        float4 q0 = __ldg((const float4*)(r0 + g.bc));
        float4 q1 = __ldg((const float4*)(r1 + g.bc));
        float e0 = 0.0f, e1 = 0.0f;
        if (g.have_e) {                    // block-uniform
            e0 = __ldg(r0 + g.bc + 4);
            e1 = __ldg(r1 + g.bc + 4);
        }
        cv[p] = make_float4(sel4(q0, g.o0), pick5(q0, e0, g.o1),
                            sel4(q1, g.o0), pick5(q1, e1, g.o1));
        s_seed[p][c] = cv[p].x * g.w00 + cv[p].y * g.w01
                     + cv[p].z * g.w10 + cv[p].w * g.w11;
        if (c == 0) s_cell[p] = make_int2(g.x0, g.y0);
    }

    // kick off tile 0 while gather results drain
    fill_tile_async(w1, 0, s_w1d, tid);

    // ---- Stage 2: layer 1 GEMM (256->128, relu), double-buffered tiles ----
    const int o = tid & 127;
    const int h = tid >> 7;
    float acc[PPB] = {0, 0, 0, 0};

    #pragma unroll
    for (int t = 0; t < CH / KT; t++) {
        if (t < CH / KT - 1) {
            fill_tile_async(w1, t + 1, s_w1d + ((t + 1) & 1) * TILE_FLOATS, tid);
            asm volatile("cp.async.wait_group 1;" ::: "memory");
        } else {
            asm volatile("cp.async.wait_group 0;" ::: "memory");
        }
        __syncthreads();   // tile t visible (and, at t=0, seeds visible)

        const float* wrow = s_w1d + (t & 1) * TILE_FLOATS + o * TSTRIDE + h * 32;
        #pragma unroll
        for (int kb = 0; kb < 4; kb++) {
            float4 wa = *(const float4*)(wrow + kb * 8);
            float4 wb = *(const float4*)(wrow + kb * 8 + 4);
            const int ch = t * KT + h * 32 + kb * 8;
            #pragma unroll
            for (int p = 0; p < PPB; p++) {
                float4 s0 = *(const float4*)&s_seed[p][ch];
                float4 s1 = *(const float4*)&s_seed[p][ch + 4];
                acc[p] += wa.x * s0.x + wa.y * s0.y + wa.z * s0.z + wa.w * s0.w
                        + wb.x * s1.x + wb.y * s1.y + wb.z * s1.z + wb.w * s1.w;
            }
        }
        __syncthreads();   // compute done before buffer reuse
    }
    #pragma unroll
    for (int p = 0; p < PPB; p++) s_part[h][o][p] = acc[p];
    __syncthreads();

    if (tid < 128) {
        float bias = __ldg(b1 + tid);
        #pragma unroll
        for (int p = 0; p < PPB; p++)
            s_h[p][tid] = fmaxf(s_part[0][tid][p] + s_part[1][tid][p] + bias, 0.0f);
    }
    __syncthreads();

    // ---- Stage 3: layer 2 (128->8) -> s_grid ----
    {
        const int p  = tid >> 6;
        const int r  = tid & 63;
        const int oo = r >> 3;            // output (= n*2 + d)
        const int j  = r & 7;             // k-slice
        const float4* w2r = (const float4*)w2 + oo * 32 + j * 4;
        const float4* hr  = (const float4*)s_h[p] + j * 4;
        float a = 0.0f;
        #pragma unroll
        for (int i = 0; i < 4; i++) {
            float4 w = __ldg(w2r + i);
            float4 hh = hr[i];
            a += w.x * hh.x + w.y * hh.y + w.z * hh.z + w.w * hh.w;
        }
        a += __shfl_down_sync(0xffffffffu, a, 4, 8);
        a += __shfl_down_sync(0xffffffffu, a, 2, 8);
        a += __shfl_down_sync(0xffffffffu, a, 1, 8);
        if (j == 0) {
            const int pt = p0 + p;
            a += __ldg(b2 + oo);
            int d = oo & 1;
            float scale = (d == 0) ? (2.0f / (WW - 1)) : (2.0f / (HH - 1));
            float base  = __ldg(kp + pt * 2 + d);
            s_grid[p][oo] = base + a * scale;
        }
    }
    __syncthreads();

    // ---- Stage 4: sampling plan (threads 0..15) ----
    if (tid < PPB * NP) {
        const int p = tid >> 2;
        const int n = tid & 3;
        float dgx = s_grid[p][n * 2 + 0];
        float dgy = s_grid[p][n * 2 + 1];
        float xx = (dgx + 1.0f) * 0.5f * (float)(WW - 1);
        float yy = (dgy + 1.0f) * 0.5f * (float)(HH - 1);
        float xf = floorf(xx), yf = floorf(yy);
        float ax1 = xx - xf, ax0 = 1.0f - ax1;
        float ay1 = yy - yf, ay0 = 1.0f - ay1;
        int dx0 = (int)xf, dy0 = (int)yf;
        int dx1 = dx0 + 1, dy1 = dy0 + 1;

        float ux0 = (dx0 >= 0 && dx0 <= WW - 1) ? 1.0f : 0.0f;
        float ux1 = (dx1 >= 0 && dx1 <= WW - 1) ? 1.0f : 0.0f;
        float uy0 = (dy0 >= 0 && dy0 <= HH - 1) ? 1.0f : 0.0f;
        float uy1 = (dy1 >= 0 && dy1 <= HH - 1) ? 1.0f : 0.0f;

        s_w[p][n] = make_float4(ax0 * ay0 * ux0 * uy0,
                                ax1 * ay0 * ux1 * uy0,
                                ax0 * ay1 * ux0 * uy1,
                                ax1 * ay1 * ux1 * uy1);
        s_fast[p][n] = (dx0 == s_cell[p].x) && (dy0 == s_cell[p].y);

        int xc0 = min(max(dx0, 0), WW - 1);
        int xc1 = min(max(dx1, 0), WW - 1);
        int yc0 = min(max(dy0, 0), HH - 1);
        int yc1 = min(max(dy1, 0), HH - 1);
        s_cd[p][n] = make_int4(yc0 * WW, yc1 * WW, xc0, xc1);
    }
    __syncthreads();

    // ---- Stage 5: resample + coalesced channel-last writes ----
    #pragma unroll
    for (int p = 0; p < PPB; p++) {
        const int pt = p0 + p;
        const float* plane = feat + planeoff[p];
        float* obase = out + (size_t)pt * (NP * CH) + c;
        #pragma unroll
        for (int n = 0; n < NP; n++) {
            float4 w = s_w[p][n];
            float r;
            if (s_fast[p][n]) {           // block-uniform branch
                r = cv[p].x * w.x + cv[p].y * w.y + cv[p].z * w.z + cv[p].w * w.w;
            } else {
                int4 cd = s_cd[p][n];
                float v00 = __ldg(plane + cd.x + cd.z);
                float v01 = __ldg(plane + cd.x + cd.w);
                float v10 = __ldg(plane + cd.y + cd.z);
                float v11 = __ldg(plane + cd.y + cd.w);
                r = v00 * w.x + v01 * w.y + v10 * w.z + v11 * w.w;
            }
            obase[n * CH] = r;
        }
    }
}

extern "C" void kernel_launch(void* const* d_in, const int* in_sizes, int n_in,
                              void* d_out, int out_size)
{
    const float* feat = (const float*)d_in[0];   // [64,256,64,64]
    const float* kp   = (const float*)d_in[1];   // [64,17,2]
    const float* w1   = (const float*)d_in[2];   // [128,256]
    const float* b1   = (const float*)d_in[3];   // [128]
    const float* w2   = (const float*)d_in[4];   // [8,128]
    const float* b2   = (const float*)d_in[5];   // [8]
    float* out = (float*)d_out;                  // [64,17,1024]

    cudaFuncSetAttribute(fused, cudaFuncAttributeMaxDynamicSharedMemorySize,
                         DSMEM_BYTES);
    fused<<<NBLK, 256, DSMEM_BYTES>>>(feat, kp, w1, b1, w2, b2, out);
}

// round 16
// speedup vs baseline: 1.2931x; 1.0122x over previous
#include <cuda_runtime.h>
#include <cuda_bf16.h>

#define BT 64
#define CH 256
#define HH 64
#define WW 64
#define JJ 17
#define NP 4
#define NPTS (BT * JJ)
#define PPB 4                    // points per block
#define NBLK (NPTS / PPB)        // 272 blocks
#define KT 64                    // channels per w1 tile
#define TSTRIDE 68               // row stride (mod 32 == 4 -> conflict-free float4 LDS)
#define TILE_FLOATS (128 * TSTRIDE)
#define DSMEM_BYTES (2 * TILE_FLOATS * 4)   // 69,632 B

typedef unsigned long long u64;

struct Geom {
    int x0, y0;
    int yc0, yc1, bc, o0, o1;
    bool have_e;
    float w00, w01, w10, w11;
};

__device__ __forceinline__ Geom make_geom(float gx, float gy) {
    Geom g;
    float x = (gx + 1.0f) * 0.5f * (float)(WW - 1);
    float y = (gy + 1.0f) * 0.5f * (float)(HH - 1);
    float x0f = floorf(x), y0f = floorf(y);
    float wx1 = x - x0f, wx0 = 1.0f - wx1;
    float wy1 = y - y0f, wy0 = 1.0f - wy1;
    g.x0 = (int)x0f; g.y0 = (int)y0f;
    int x0 = g.x0, y0 = g.y0;
    int x1 = x0 + 1, y1 = y0 + 1;
    float vx0 = (x0 >= 0 && x0 <= WW - 1) ? 1.0f : 0.0f;
    float vx1 = (x1 >= 0 && x1 <= WW - 1) ? 1.0f : 0.0f;
    float vy0 = (y0 >= 0 && y0 <= HH - 1) ? 1.0f : 0.0f;
    float vy1 = (y1 >= 0 && y1 <= HH - 1) ? 1.0f : 0.0f;
    int xc0 = min(max(x0, 0), WW - 1);
    int xc1 = min(max(x1, 0), WW - 1);
    g.yc0 = min(max(y0, 0), HH - 1);
    g.yc1 = min(max(y1, 0), HH - 1);
    g.bc  = xc0 & ~3;
    g.o0  = xc0 - g.bc;
    g.o1  = xc1 - g.bc;
    g.have_e = (g.o1 == 4);
    g.w00 = wx0 * wy0 * vx0 * vy0;
    g.w01 = wx1 * wy0 * vx1 * vy0;
    g.w10 = wx0 * wy1 * vx0 * vy1;
    g.w11 = wx1 * wy1 * vx1 * vy1;
    return g;
}

__device__ __forceinline__ float sel4(float4 q, int i) {
    float r = q.x;
    if (i == 1) r = q.y;
    else if (i == 2) r = q.z;
    else if (i == 3) r = q.w;
    return r;
}
__device__ __forceinline__ float pick5(float4 q, float e, int i) {
    return (i == 4) ? e : sel4(q, i);
}

__device__ __forceinline__ void fma2(u64& acc, u64 a, u64 b) {
    asm("fma.rn.f32x2 %0, %1, %2, %3;" : "=l"(acc) : "l"(a), "l"(b), "l"(acc));
}
__device__ __forceinline__ float unpack_sum(u64 v) {
    float lo, hi;
    asm("mov.b64 {%0, %1}, %2;" : "=f"(lo), "=f"(hi) : "l"(v));
    return lo + hi;
}

// async-copy one KT-channel w1 tile into smem (row-major [128][TSTRIDE]), L2-only
__device__ __forceinline__ void fill_tile_async(
    const float* __restrict__ w1, int t, float* tile, int tid)
{
    unsigned dst_base = (unsigned)__cvta_generic_to_shared(tile);
    #pragma unroll
    for (int j = 0; j < 8; j++) {
        int L  = tid + j * 256;
        int oo = L >> 4;
        int k4 = L & 15;
        const float* src = w1 + oo * CH + t * KT + k4 * 4;
        unsigned dst = dst_base + (oo * TSTRIDE + k4 * 4) * 4;
        asm volatile("cp.async.cg.shared.global [%0], [%1], 16;"
                     :: "r"(dst), "l"(src) : "memory");
    }
    asm volatile("cp.async.commit_group;" ::: "memory");
}

// ───────────── Fully fused kernel: 272 blocks x 256 threads, 4 points each ─────────────
__global__ __launch_bounds__(256)
void fused(const float* __restrict__ feat, const float* __restrict__ kp,
           const float* __restrict__ w1, const float* __restrict__ b1,
           const float* __restrict__ w2, const float* __restrict__ b2,
           float* __restrict__ out)
{
    extern __shared__ float s_w1d[];                  // 2 x [128][TSTRIDE]
    __shared__ __align__(16) float s_seed[PPB][CH];   // 4 KB
    __shared__ float s_part[2][128][PPB + 1];         // 5 KB
    __shared__ __align__(16) float s_h[PPB][128];     // 2 KB
    __shared__ float  s_grid[PPB][2 * NP];
    __shared__ int2   s_cell[PPB];
    __shared__ float4 s_w[PPB][NP];
    __shared__ int4   s_cd[PPB][NP];
    __shared__ int    s_fast[PPB][NP];

    const int tid = threadIdx.x;
    const int c   = tid;
    const int p0  = blockIdx.x * PPB;

    // ---- Stage 1a: geometry + issue ALL gather loads (front-batched) ----
    Geom gm[PPB];
    float4 q0[PPB], q1[PPB];
    float  e0[PPB], e1[PPB];
    unsigned planeoff[PPB];
    #pragma unroll
    for (int p = 0; p < PPB; p++) {
        const int pt = p0 + p;
        gm[p] = make_geom(__ldg(kp + pt * 2 + 0), __ldg(kp + pt * 2 + 1));
        planeoff[p] = ((unsigned)(pt / JJ) * CH + c) * (HH * WW);
        const float* plane = feat + planeoff[p];
        const float* r0 = plane + gm[p].yc0 * WW;
        const float* r1 = plane + gm[p].yc1 * WW;
        q0[p] = __ldg((const float4*)(r0 + gm[p].bc));
        q1[p] = __ldg((const float4*)(r1 + gm[p].bc));
        e0[p] = 0.0f; e1[p] = 0.0f;
        if (gm[p].have_e) {               // block-uniform
            e0[p] = __ldg(r0 + gm[p].bc + 4);
            e1[p] = __ldg(r1 + gm[p].bc + 4);
        }
    }
    // kick off w1 tile 0 (independent of gather)
    fill_tile_async(w1, 0, s_w1d, tid);

    // ---- Stage 1b: seeds + register corner quads ----
    float4 cv[PPB];
    #pragma unroll
    for (int p = 0; p < PPB; p++) {
        cv[p] = make_float4(sel4(q0[p], gm[p].o0), pick5(q0[p], e0[p], gm[p].o1),
                            sel4(q1[p], gm[p].o0), pick5(q1[p], e1[p], gm[p].o1));
        s_seed[p][c] = cv[p].x * gm[p].w00 + cv[p].y * gm[p].w01
                     + cv[p].z * gm[p].w10 + cv[p].w * gm[p].w11;
        if (c == 0) s_cell[p] = make_int2(gm[p].x0, gm[p].y0);
    }

    // ---- Stage 2: layer 1 GEMM (256->128, relu), f32x2-packed, double-buffered ----
    const int o = tid & 127;
    const int h = tid >> 7;
    u64 acc0[PPB] = {0ull, 0ull, 0ull, 0ull};
    u64 acc1[PPB] = {0ull, 0ull, 0ull, 0ull};

    #pragma unroll
    for (int t = 0; t < CH / KT; t++) {
        if (t < CH / KT - 1) {
            fill_tile_async(w1, t + 1, s_w1d + ((t + 1) & 1) * TILE_FLOATS, tid);
            asm volatile("cp.async.wait_group 1;" ::: "memory");
        } else {
            asm volatile("cp.async.wait_group 0;" ::: "memory");
        }
        __syncthreads();   // tile t (and, at t=0, seeds) visible

        const float* wrow = s_w1d + (t & 1) * TILE_FLOATS + o * TSTRIDE + h * 32;
        #pragma unroll
        for (int kb = 0; kb < 4; kb++) {
            ulonglong2 wA = *(const ulonglong2*)(wrow + kb * 8);       // pairs c0c1,c2c3
            ulonglong2 wB = *(const ulonglong2*)(wrow + kb * 8 + 4);   // pairs c4c5,c6c7
            const int ch = t * KT + h * 32 + kb * 8;
            #pragma unroll
            for (int p = 0; p < PPB; p++) {
                ulonglong2 sA = *(const ulonglong2*)&s_seed[p][ch];
                ulonglong2 sB = *(const ulonglong2*)&s_seed[p][ch + 4];
                fma2(acc0[p], wA.x, sA.x);
                fma2(acc1[p], wA.y, sA.y);
                fma2(acc0[p], wB.x, sB.x);
                fma2(acc1[p], wB.y, sB.y);
            }
        }
        __syncthreads();   // compute done before buffer reuse
    }
    #pragma unroll
    for (int p = 0; p < PPB; p++)
        s_part[h][o][p] = unpack_sum(acc0[p]) + unpack_sum(acc1[p]);
    __syncthreads();

    if (tid < 128) {
        float bias = __ldg(b1 + tid);
        #pragma unroll
        for (int p = 0; p < PPB; p++)
            s_h[p][tid] = fmaxf(s_part[0][tid][p] + s_part[1][tid][p] + bias, 0.0f);
    }
    __syncthreads();

    // ---- Stage 3: layer 2 (128->8) -> s_grid ----
    {
        const int p  = tid >> 6;
        const int r  = tid & 63;
        const int oo = r >> 3;            // output (= n*2 + d)
        const int j  = r & 7;             // k-slice
        const float4* w2r = (const float4*)w2 + oo * 32 + j * 4;
        const float4* hr  = (const float4*)s_h[p] + j * 4;
        float a = 0.0f;
        #pragma unroll
        for (int i = 0; i < 4; i++) {
            float4 w = __ldg(w2r + i);
            float4 hh = hr[i];
            a += w.x * hh.x + w.y * hh.y + w.z * hh.z + w.w * hh.w;
        }
        a += __shfl_down_sync(0xffffffffu, a, 4, 8);
        a += __shfl_down_sync(0xffffffffu, a, 2, 8);
        a += __shfl_down_sync(0xffffffffu, a, 1, 8);
        if (j == 0) {
            const int pt = p0 + p;
            a += __ldg(b2 + oo);
            int d = oo & 1;
            float scale = (d == 0) ? (2.0f / (WW - 1)) : (2.0f / (HH - 1));
            float base  = __ldg(kp + pt * 2 + d);
            s_grid[p][oo] = base + a * scale;
        }
    }
    __syncthreads();

    // ---- Stage 4: sampling plan (threads 0..15) ----
    if (tid < PPB * NP) {
        const int p = tid >> 2;
        const int n = tid & 3;
        float dgx = s_grid[p][n * 2 + 0];
        float dgy = s_grid[p][n * 2 + 1];
        float xx = (dgx + 1.0f) * 0.5f * (float)(WW - 1);
        float yy = (dgy + 1.0f) * 0.5f * (float)(HH - 1);
        float xf = floorf(xx), yf = floorf(yy);
        float ax1 = xx - xf, ax0 = 1.0f - ax1;
        float ay1 = yy - yf, ay0 = 1.0f - ay1;
        int dx0 = (int)xf, dy0 = (int)yf;
        int dx1 = dx0 + 1, dy1 = dy0 + 1;

        float ux0 = (dx0 >= 0 && dx0 <= WW - 1) ? 1.0f : 0.0f;
        float ux1 = (dx1 >= 0 && dx1 <= WW - 1) ? 1.0f : 0.0f;
        float uy0 = (dy0 >= 0 && dy0 <= HH - 1) ? 1.0f : 0.0f;
        float uy1 = (dy1 >= 0 && dy1 <= HH - 1) ? 1.0f : 0.0f;

        s_w[p][n] = make_float4(ax0 * ay0 * ux0 * uy0,
                                ax1 * ay0 * ux1 * uy0,
                                ax0 * ay1 * ux0 * uy1,
                                ax1 * ay1 * ux1 * uy1);
        s_fast[p][n] = (dx0 == s_cell[p].x) && (dy0 == s_cell[p].y);

        int xc0 = min(max(dx0, 0), WW - 1);
        int xc1 = min(max(dx1, 0), WW - 1);
        int yc0 = min(max(dy0, 0), HH - 1);
        int yc1 = min(max(dy1, 0), HH - 1);
        s_cd[p][n] = make_int4(yc0 * WW, yc1 * WW, xc0, xc1);
    }
    __syncthreads();

    // ---- Stage 5: resample + coalesced channel-last writes ----
    #pragma unroll
    for (int p = 0; p < PPB; p++) {
        const int pt = p0 + p;
        const float* plane = feat + planeoff[p];
        float* obase = out + (size_t)pt * (NP * CH) + c;
        #pragma unroll
        for (int n = 0; n < NP; n++) {
            float4 w = s_w[p][n];
            float r;
            if (s_fast[p][n]) {           // block-uniform branch
                r = cv[p].x * w.x + cv[p].y * w.y + cv[p].z * w.z + cv[p].w * w.w;
            } else {
                int4 cd = s_cd[p][n];
                float v00 = __ldg(plane + cd.x + cd.z);
                float v01 = __ldg(plane + cd.x + cd.w);
                float v10 = __ldg(plane + cd.y + cd.z);
                float v11 = __ldg(plane + cd.y + cd.w);
                r = v00 * w.x + v01 * w.y + v10 * w.z + v11 * w.w;
            }
            obase[n * CH] = r;
        }
    }
}

extern "C" void kernel_launch(void* const* d_in, const int* in_sizes, int n_in,
                              void* d_out, int out_size)
{
    const float* feat = (const float*)d_in[0];   // [64,256,64,64]
    const float* kp   = (const float*)d_in[1];   // [64,17,2]
    const float* w1   = (const float*)d_in[2];   // [128,256]
    const float* b1   = (const float*)d_in[3];   // [128]
    const float* w2   = (const float*)d_in[4];   // [8,128]
    const float* b2   = (const float*)d_in[5];   // [8]
    float* out = (float*)d_out;                  // [64,17,1024]

    cudaFuncSetAttribute(fused, cudaFuncAttributeMaxDynamicSharedMemorySize,
                         DSMEM_BYTES);
    fused<<<NBLK, 256, DSMEM_BYTES>>>(feat, kp, w1, b1, w2, b2, out);
}